// round 7
// baseline (speedup 1.0000x reference)
#include <cuda_runtime.h>
#include <cuda_bf16.h>
#include <cstdint>

// Problem constants (B=1 fixed)
#define S_LEN   2048
#define HID     6144
#define QKV_OUT 6400   // HID + 2*128
#define NH      48
#define HD      128

// Scratch (no cudaMalloc allowed)
__device__ float g_qkv [S_LEN * QKV_OUT];
__device__ float g_attn[S_LEN * HID];

// ---------------------------------------------------------------------------
// helpers
// ---------------------------------------------------------------------------
__device__ __forceinline__ uint32_t smem_u32(const void* p) {
    uint32_t a;
    asm("{ .reg .u64 t; cvta.to.shared.u64 t, %1; cvt.u32.u64 %0, t; }"
        : "=r"(a) : "l"(p));
    return a;
}

__device__ __forceinline__ void mma_bf16(float* d, const uint32_t* a, const uint32_t* b) {
    asm volatile(
        "mma.sync.aligned.m16n8k16.row.col.f32.bf16.bf16.f32 "
        "{%0,%1,%2,%3}, {%4,%5,%6,%7}, {%8,%9}, {%0,%1,%2,%3};"
        : "+f"(d[0]), "+f"(d[1]), "+f"(d[2]), "+f"(d[3])
        : "r"(a[0]), "r"(a[1]), "r"(a[2]), "r"(a[3]), "r"(b[0]), "r"(b[1]));
}

__device__ __forceinline__ void ldsm_x4(uint32_t* r, uint32_t addr) {
    asm volatile("ldmatrix.sync.aligned.m8n8.x4.shared.b16 {%0,%1,%2,%3}, [%4];"
                 : "=r"(r[0]), "=r"(r[1]), "=r"(r[2]), "=r"(r[3]) : "r"(addr));
}
__device__ __forceinline__ void ldsm_x2(uint32_t* r, uint32_t addr) {
    asm volatile("ldmatrix.sync.aligned.m8n8.x2.shared.b16 {%0,%1}, [%2];"
                 : "=r"(r[0]), "=r"(r[1]) : "r"(addr));
}
__device__ __forceinline__ void ldsm_x2_t(uint32_t& r0, uint32_t& r1, uint32_t addr) {
    asm volatile("ldmatrix.sync.aligned.m8n8.x2.trans.shared.b16 {%0,%1}, [%2];"
                 : "=r"(r0), "=r"(r1) : "r"(addr));
}

// split two floats into bf16 hi pair + bf16 lo (residual) pair
__device__ __forceinline__ void pack_split2(float x, float y, uint32_t& hi, uint32_t& lo) {
    __nv_bfloat162 h = __floats2bfloat162_rn(x, y);
    float2 hf = __bfloat1622float2(h);
    __nv_bfloat162 l = __floats2bfloat162_rn(x - hf.x, y - hf.y);
    hi = *reinterpret_cast<uint32_t*>(&h);
    lo = *reinterpret_cast<uint32_t*>(&l);
}

// load 16 consecutive floats, split, store 8 hi u32 at hi[], 8 lo u32 at lo[]
__device__ __forceinline__ void split16(const float* src, uint32_t* hi, uint32_t* lo,
                                        float scale) {
    #pragma unroll
    for (int i = 0; i < 4; i++) {
        float4 f = *(const float4*)(src + i * 4);
        f.x *= scale; f.y *= scale; f.z *= scale; f.w *= scale;
        uint32_t h0, l0, h1, l1;
        pack_split2(f.x, f.y, h0, l0);
        pack_split2(f.z, f.w, h1, l1);
        hi[i * 2] = h0; hi[i * 2 + 1] = h1;
        lo[i * 2] = l0; lo[i * 2 + 1] = l1;
    }
}

// ---------------------------------------------------------------------------
// bf16-split GEMM: C[M,N] = A[M,K] * B[N,K]^T + bias[N]
// CTA 128x128, BK=16, 128 threads, 4 warps (2x2), warp tile 64x64.
// Row pitch 20 u32 (80B): 8 hi | 8 lo | 4 pad. 2 CTAs/SM, 256 regs/thread.
// ---------------------------------------------------------------------------
#define GP2   20
#define GTILE (128 * GP2)      // 2560 u32 per tile
#define GSTG  (2 * GTILE)      // A + B per stage

__global__ void __launch_bounds__(128, 2) gemm_bf16s(
    const float* __restrict__ A, const float* __restrict__ B,
    const float* __restrict__ bias, float* __restrict__ C,
    int M, int N, int K)
{
    extern __shared__ uint32_t gsm[];
    const uint32_t smb = smem_u32(gsm);

    const int tid = threadIdx.x;
    const int wid = tid >> 5, lid = tid & 31;
    const int g   = lid >> 2;
    const int t4  = lid & 3;
    const int wr  = wid >> 1;       // 0..1 (M, 64 rows)
    const int wc  = wid & 1;        // 0..1 (N, 64 cols)

    const int bm = blockIdx.y * 128, bn = blockIdx.x * 128;

    // loader: thread t owns full row t (16 floats per stage)
    const float* Ag = A + (long)(bm + tid) * K;
    const float* Bg = B + (long)(bn + tid) * K;
    const uint32_t sto = (uint32_t)(tid * GP2);

    // ldmatrix lane addresses (bytes within a tile)
    const uint32_t a_row = (uint32_t)(((wr * 64 + (lid & 15)) * GP2 + (lid >> 4) * 4) * 4);
    const uint32_t b_row = (uint32_t)(((wc * 64 + (lid & 7)) * GP2 + (((lid & 15) >> 3) & 1) * 4) * 4);

    float acc[4][8][4];
    #pragma unroll
    for (int i = 0; i < 4; i++)
        #pragma unroll
        for (int j = 0; j < 8; j++)
            #pragma unroll
            for (int k = 0; k < 4; k++) acc[i][j][k] = 0.0f;

    const int NS = K >> 4;
    float4 ar[4], br[4];

    // prologue: stage 0
    #pragma unroll
    for (int i = 0; i < 4; i++) {
        ar[i] = *(const float4*)(Ag + i * 4);
        br[i] = *(const float4*)(Bg + i * 4);
    }
    {
        uint32_t hi[8], lo[8];
        split16((const float*)ar, hi, lo, 1.0f);
        *(uint4*)(gsm + sto)      = *(uint4*)(hi);
        *(uint4*)(gsm + sto + 4)  = *(uint4*)(hi + 4);
        *(uint4*)(gsm + sto + 8)  = *(uint4*)(lo);
        *(uint4*)(gsm + sto + 12) = *(uint4*)(lo + 4);
        split16((const float*)br, hi, lo, 1.0f);
        *(uint4*)(gsm + GTILE + sto)      = *(uint4*)(hi);
        *(uint4*)(gsm + GTILE + sto + 4)  = *(uint4*)(hi + 4);
        *(uint4*)(gsm + GTILE + sto + 8)  = *(uint4*)(lo);
        *(uint4*)(gsm + GTILE + sto + 12) = *(uint4*)(lo + 4);
    }
    __syncthreads();

    for (int s = 0; s < NS; s++) {
        if (s + 1 < NS) {
            const long koff = 16L * (s + 1);
            #pragma unroll
            for (int i = 0; i < 4; i++) {
                ar[i] = *(const float4*)(Ag + koff + i * 4);
                br[i] = *(const float4*)(Bg + koff + i * 4);
            }
        }

        // compute on slot s&1
        {
            const uint32_t abase = smb + (uint32_t)((s & 1) * GSTG) * 4u + a_row;
            const uint32_t bbase = smb + (uint32_t)((s & 1) * GSTG + GTILE) * 4u + b_row;

            uint32_t ah[4][4], al[4][4];
            #pragma unroll
            for (int mt = 0; mt < 4; mt++) {
                ldsm_x4(ah[mt], abase + mt * (16 * GP2 * 4));
                ldsm_x4(al[mt], abase + mt * (16 * GP2 * 4) + 32);
            }
            #pragma unroll
            for (int nt = 0; nt < 8; nt++) {
                uint32_t bh[2], bl[2];
                ldsm_x2(bh, bbase + nt * (8 * GP2 * 4));
                ldsm_x2(bl, bbase + nt * (8 * GP2 * 4) + 32);
                #pragma unroll
                for (int mt = 0; mt < 4; mt++) mma_bf16(acc[mt][nt], ah[mt], bh);
                #pragma unroll
                for (int mt = 0; mt < 4; mt++) mma_bf16(acc[mt][nt], ah[mt], bl);
                #pragma unroll
                for (int mt = 0; mt < 4; mt++) mma_bf16(acc[mt][nt], al[mt], bh);
            }
        }

        if (s + 1 < NS) {
            uint32_t* dst = gsm + ((s + 1) & 1) * GSTG;
            uint32_t hi[8], lo[8];
            split16((const float*)ar, hi, lo, 1.0f);
            *(uint4*)(dst + sto)      = *(uint4*)(hi);
            *(uint4*)(dst + sto + 4)  = *(uint4*)(hi + 4);
            *(uint4*)(dst + sto + 8)  = *(uint4*)(lo);
            *(uint4*)(dst + sto + 12) = *(uint4*)(lo + 4);
            split16((const float*)br, hi, lo, 1.0f);
            *(uint4*)(dst + GTILE + sto)      = *(uint4*)(hi);
            *(uint4*)(dst + GTILE + sto + 4)  = *(uint4*)(hi + 4);
            *(uint4*)(dst + GTILE + sto + 8)  = *(uint4*)(lo);
            *(uint4*)(dst + GTILE + sto + 12) = *(uint4*)(lo + 4);
            __syncthreads();
        }
    }

    // epilogue
    #pragma unroll
    for (int mt = 0; mt < 4; mt++) {
        const int row = bm + wr * 64 + mt * 16 + g;
        #pragma unroll
        for (int nt = 0; nt < 8; nt++) {
            const int col = bn + wc * 64 + nt * 8 + t4 * 2;
            const float b0 = bias[col], b1 = bias[col + 1];
            float2 lo, hi;
            lo.x = acc[mt][nt][0] + b0; lo.y = acc[mt][nt][1] + b1;
            hi.x = acc[mt][nt][2] + b0; hi.y = acc[mt][nt][3] + b1;
            *(float2*)&C[(long)row * N + col]       = lo;
            *(float2*)&C[(long)(row + 8) * N + col] = hi;
        }
    }
}

// ---------------------------------------------------------------------------
// MQA causal flash attention, bf16-split HMMA (unchanged from R6).
// ---------------------------------------------------------------------------
#define QP 132

__global__ void __launch_bounds__(128) mqa_flash_hmma(
    const float* __restrict__ qkv, float* __restrict__ attn_out)
{
    extern __shared__ uint32_t asm_[];
    uint32_t* q_s = asm_;                 // [64][QP]
    uint32_t* k_s = q_s + 64 * QP;
    uint32_t* v_s = k_s + 64 * QP;

    const int h  = blockIdx.y;
    const int bq = blockIdx.x;
    const int q0 = bq * 64;
    const int tid = threadIdx.x;
    const int wid = tid >> 5, lid = tid & 31;
    const int g = lid >> 2, t4 = lid & 3;

    const uint32_t v_base = smem_u32(v_s);

    const int lr  = tid >> 1;            // row 0..63
    const int lc0 = (tid & 1) * 16;      // chunk base 0 or 16

    // Load Q tile (pre-scaled by 1/sqrt(128)), split into hi/lo bf16.
    {
        const float* src = qkv + (long)(q0 + lr) * QKV_OUT + h * HD;
        uint32_t* dst = q_s + lr * QP;
        #pragma unroll
        for (int jj = 0; jj < 4; jj++) {
            const int c16 = lc0 + 32 * jj;   // covers d = 0..127
            split16(src + c16, dst + (c16 >> 1), dst + (c16 >> 1) + 64,
                    0.08838834764831845f);
        }
    }

    float o[16][4];
    #pragma unroll
    for (int i = 0; i < 16; i++)
        #pragma unroll
        for (int j = 0; j < 4; j++) o[i][j] = 0.0f;
    float m0 = -1e30f, m1 = -1e30f, l0 = 0.0f, l1 = 0.0f;

    const int row0 = q0 + wid * 16 + g;
    const int row1 = row0 + 8;

    for (int kt = 0; kt <= bq; kt++) {
        __syncthreads();   // Q ready / previous-iter smem reads done
        {
            const float* kp = qkv + (long)(kt * 64 + lr) * QKV_OUT + HID;
            uint32_t* kd = k_s + lr * QP;
            uint32_t* vd = v_s + lr * QP;
            #pragma unroll
            for (int jj = 0; jj < 4; jj++) {
                const int c16 = lc0 + 32 * jj;
                split16(kp + c16,      kd + (c16 >> 1), kd + (c16 >> 1) + 64, 1.0f);
                split16(kp + HD + c16, vd + (c16 >> 1), vd + (c16 >> 1) + 64, 1.0f);
            }
        }
        __syncthreads();

        // ---- S = Q K^T (3-term bf16) ----
        float s[8][4];
        #pragma unroll
        for (int nt = 0; nt < 8; nt++)
            #pragma unroll
            for (int j = 0; j < 4; j++) s[nt][j] = 0.0f;

        const uint32_t* qb = q_s + (wid * 16) * QP;
        #pragma unroll
        for (int ks = 0; ks < 8; ks++) {
            uint32_t ah[4], al[4];
            const int ro = g * QP + ks * 8 + t4;
            ah[0] = qb[ro];          ah[1] = qb[ro + 8 * QP];
            ah[2] = qb[ro + 4];      ah[3] = qb[ro + 8 * QP + 4];
            al[0] = qb[ro + 64];     al[1] = qb[ro + 8 * QP + 64];
            al[2] = qb[ro + 68];     al[3] = qb[ro + 8 * QP + 68];
            #pragma unroll
            for (int nt = 0; nt < 8; nt++) {
                const int rb = (nt * 8 + g) * QP + ks * 8 + t4;
                uint32_t bh[2] = { k_s[rb],      k_s[rb + 4]  };
                uint32_t bl[2] = { k_s[rb + 64], k_s[rb + 68] };
                mma_bf16(s[nt], ah, bh);
                mma_bf16(s[nt], ah, bl);
                mma_bf16(s[nt], al, bh);
            }
        }

        // causal mask (diagonal tile only)
        if (kt == bq) {
            #pragma unroll
            for (int nt = 0; nt < 8; nt++) {
                const int col = kt * 64 + nt * 8 + 2 * t4;
                if (col     > row0) s[nt][0] = -1e30f;
                if (col + 1 > row0) s[nt][1] = -1e30f;
                if (col     > row1) s[nt][2] = -1e30f;
                if (col + 1 > row1) s[nt][3] = -1e30f;
            }
        }

        // ---- online softmax (rows g and g+8) ----
        float mt0 = -1e30f, mt1 = -1e30f;
        #pragma unroll
        for (int nt = 0; nt < 8; nt++) {
            mt0 = fmaxf(mt0, fmaxf(s[nt][0], s[nt][1]));
            mt1 = fmaxf(mt1, fmaxf(s[nt][2], s[nt][3]));
        }
        mt0 = fmaxf(mt0, __shfl_xor_sync(0xffffffffu, mt0, 1));
        mt0 = fmaxf(mt0, __shfl_xor_sync(0xffffffffu, mt0, 2));
        mt1 = fmaxf(mt1, __shfl_xor_sync(0xffffffffu, mt1, 1));
        mt1 = fmaxf(mt1, __shfl_xor_sync(0xffffffffu, mt1, 2));

        const float mn0 = fmaxf(m0, mt0), mn1 = fmaxf(m1, mt1);
        const float al0 = __expf(m0 - mn0), al1 = __expf(m1 - mn1);

        float ps0 = 0.0f, ps1 = 0.0f;
        #pragma unroll
        for (int nt = 0; nt < 8; nt++) {
            s[nt][0] = __expf(s[nt][0] - mn0);
            s[nt][1] = __expf(s[nt][1] - mn0);
            s[nt][2] = __expf(s[nt][2] - mn1);
            s[nt][3] = __expf(s[nt][3] - mn1);
            ps0 += s[nt][0] + s[nt][1];
            ps1 += s[nt][2] + s[nt][3];
        }
        ps0 += __shfl_xor_sync(0xffffffffu, ps0, 1);
        ps0 += __shfl_xor_sync(0xffffffffu, ps0, 2);
        ps1 += __shfl_xor_sync(0xffffffffu, ps1, 1);
        ps1 += __shfl_xor_sync(0xffffffffu, ps1, 2);
        l0 = l0 * al0 + ps0; m0 = mn0;
        l1 = l1 * al1 + ps1; m1 = mn1;

        #pragma unroll
        for (int nt = 0; nt < 16; nt++) {
            o[nt][0] *= al0; o[nt][1] *= al0;
            o[nt][2] *= al1; o[nt][3] *= al1;
        }

        // ---- O += P V (3-term bf16); P frags packed directly from S frags ----
        #pragma unroll
        for (int jj = 0; jj < 4; jj++) {
            uint32_t ph[4], pl[4];
            pack_split2(s[2*jj][0],   s[2*jj][1],   ph[0], pl[0]);
            pack_split2(s[2*jj][2],   s[2*jj][3],   ph[1], pl[1]);
            pack_split2(s[2*jj+1][0], s[2*jj+1][1], ph[2], pl[2]);
            pack_split2(s[2*jj+1][2], s[2*jj+1][3], ph[3], pl[3]);

            const uint32_t rowaddr = v_base + (uint32_t)(((jj * 16 + (lid & 15)) * QP) * 4);
            #pragma unroll
            for (int nt = 0; nt < 16; nt++) {
                uint32_t bh[2], bl[2];
                ldsm_x2_t(bh[0], bh[1], rowaddr + nt * 16);
                ldsm_x2_t(bl[0], bl[1], rowaddr + 256 + nt * 16);
                mma_bf16(o[nt], ph, bh);
                mma_bf16(o[nt], ph, bl);
                mma_bf16(o[nt], pl, bh);
            }
        }
    }

    // epilogue
    const float i0 = 1.0f / l0, i1 = 1.0f / l1;
    #pragma unroll
    for (int nt = 0; nt < 16; nt++) {
        const int d = nt * 8 + 2 * t4;
        float2 a, b;
        a.x = o[nt][0] * i0; a.y = o[nt][1] * i0;
        b.x = o[nt][2] * i1; b.y = o[nt][3] * i1;
        *(float2*)&attn_out[(long)row0 * HID + h * HD + d] = a;
        *(float2*)&attn_out[(long)row1 * HID + h * HD + d] = b;
    }
}

// ---------------------------------------------------------------------------
extern "C" void kernel_launch(void* const* d_in, const int* in_sizes, int n_in,
                              void* d_out, int out_size)
{
    const float* x    = (const float*)d_in[0];
    const float* wqkv = (const float*)d_in[1];
    const float* bqkv = (const float*)d_in[2];
    const float* wo   = (const float*)d_in[3];
    const float* bo   = (const float*)d_in[4];
    float* out = (float*)d_out;

    float *qkv_buf, *attn_buf;
    cudaGetSymbolAddress((void**)&qkv_buf,  g_qkv);
    cudaGetSymbolAddress((void**)&attn_buf, g_attn);

    const int gemm_smem = 2 * GSTG * sizeof(uint32_t);     // 40960
    cudaFuncSetAttribute(gemm_bf16s,
                         cudaFuncAttributeMaxDynamicSharedMemorySize, gemm_smem);

    const int attn_smem = 3 * 64 * QP * sizeof(uint32_t);  // 101376
    cudaFuncSetAttribute(mqa_flash_hmma,
                         cudaFuncAttributeMaxDynamicSharedMemorySize, attn_smem);

    // 1) QKV projection
    {
        dim3 grid(QKV_OUT / 128, S_LEN / 128);
        gemm_bf16s<<<grid, 128, gemm_smem>>>(x, wqkv, bqkv, qkv_buf,
                                             S_LEN, QKV_OUT, HID);
    }
    // 2) attention
    {
        dim3 grid(S_LEN / 64, NH);
        mqa_flash_hmma<<<grid, 128, attn_smem>>>(qkv_buf, attn_buf);
    }
    // 3) output projection
    {
        dim3 grid(HID / 128, S_LEN / 128);
        gemm_bf16s<<<grid, 128, gemm_smem>>>(attn_buf, wo, bo, out,
                                             S_LEN, HID, HID);
    }
}